// round 1
// baseline (speedup 1.0000x reference)
#include <cuda_runtime.h>

#define NN 50000
#define NE 800000
#define F1 128
#define F2 64

// ---------------- scratch (static device globals; no allocation) ----------------
__device__ float g_degout[NN];
__device__ float g_degin[NN];
__device__ float g_sout[NN];      // rsqrt(clamp(deg_out,1))
__device__ float g_sin[NN];       // rsqrt(clamp(deg_in,1))
__device__ float g_h1[NN * F1];   // feat * s_out
__device__ float g_agg1[NN * F1]; // segment_sum(h1[src]) by dst
__device__ float g_h2[NN * F2];   // (relu(gc1)*s_out) @ W2
__device__ float g_agg2[NN * F2]; // segment_sum(h2[src]) by dst

// ---------------- small prep kernels ----------------
__global__ void k_zero_deg() {
    int i = blockIdx.x * blockDim.x + threadIdx.x;
    if (i < NN) { g_degout[i] = 0.f; g_degin[i] = 0.f; }
}

__global__ void k_deg(const int* __restrict__ src, const int* __restrict__ dst) {
    int e = blockIdx.x * blockDim.x + threadIdx.x;
    if (e < NE) {
        atomicAdd(&g_degout[src[e]], 1.0f);
        atomicAdd(&g_degin[dst[e]], 1.0f);
    }
}

__global__ void k_scales() {
    int i = blockIdx.x * blockDim.x + threadIdx.x;
    if (i < NN) {
        g_sout[i] = rsqrtf(fmaxf(g_degout[i], 1.0f));
        g_sin[i]  = rsqrtf(fmaxf(g_degin[i], 1.0f));
    }
}

// h1 = feat * s_out[row];  zero agg1.  (N*32 float4 elements)
__global__ void k_prep1(const float4* __restrict__ feat4) {
    int i = blockIdx.x * blockDim.x + threadIdx.x;
    if (i < NN * (F1 / 4)) {
        int row = i >> 5;  // F1/4 = 32 float4 per row
        float s = g_sout[row];
        float4 v = feat4[i];
        v.x *= s; v.y *= s; v.z *= s; v.w *= s;
        ((float4*)g_h1)[i] = v;
        ((float4*)g_agg1)[i] = make_float4(0.f, 0.f, 0.f, 0.f);
    }
}

__global__ void k_zero2() {
    int i = blockIdx.x * blockDim.x + threadIdx.x;
    if (i < NN * (F2 / 4)) ((float4*)g_agg2)[i] = make_float4(0.f, 0.f, 0.f, 0.f);
}

// ---------------- edge scatter 1: one warp per edge, float4 vector atomics ----------------
__global__ void k_scat1(const int* __restrict__ src, const int* __restrict__ dst) {
    int w = (blockIdx.x * blockDim.x + threadIdx.x) >> 5;
    int lane = threadIdx.x & 31;
    if (w >= NE) return;
    int s = __ldg(&src[w]);
    int d = __ldg(&dst[w]);
    float4 v = ((const float4*)g_h1)[s * 32 + lane];
    atomicAdd(&((float4*)g_agg1)[d * 32 + lane], v);  // sm_90+: vector RED
}

// ---------------- edge scatter 2: 16 lanes per edge (64 floats) ----------------
__global__ void k_scat2(const int* __restrict__ src, const int* __restrict__ dst) {
    int t = blockIdx.x * blockDim.x + threadIdx.x;
    int e = t >> 4;
    int sub = t & 15;
    if (e >= NE) return;
    int s = __ldg(&src[e]);
    int d = __ldg(&dst[e]);
    float4 v = ((const float4*)g_h2)[s * 16 + sub];
    atomicAdd(&((float4*)g_agg2)[d * 16 + sub], v);
}

// ---------------- fused double GEMM ----------------
// per row r:  v = relu((agg1[r] @ W1) * s_in[r] + b1) * s_out[r]   (128 vec)
//             h2[r] = v @ W2                                       (64 vec)
// W1 (64KB) + W2 (32KB) in smem; 256 threads; each warp processes 4 rows/pass.
#define RPB 64  // rows per block (2 passes of 8 warps * 4 rows)

__device__ __forceinline__ void fma4(float4& acc, float a, const float4& w) {
    acc.x = fmaf(a, w.x, acc.x);
    acc.y = fmaf(a, w.y, acc.y);
    acc.z = fmaf(a, w.z, acc.z);
    acc.w = fmaf(a, w.w, acc.w);
}

__global__ __launch_bounds__(256, 2)
void k_gemm(const float4* __restrict__ W1g, const float4* __restrict__ W2g,
            const float* __restrict__ b1g) {
    extern __shared__ float sm[];
    float* sW1 = sm;                   // 16384 floats
    float* sW2 = sm + F1 * F1;         // 8192 floats
    float* sBuf = sm + F1 * F1 + F1 * F2;  // 8 warps * 4 rows * 128 = 4096 floats

    int tid = threadIdx.x;
    float4* sW1_4 = (float4*)sW1;
    float4* sW2_4 = (float4*)sW2;
    #pragma unroll 4
    for (int i = tid; i < (F1 * F1) / 4; i += 256) sW1_4[i] = W1g[i];
    #pragma unroll 2
    for (int i = tid; i < (F1 * F2) / 4; i += 256) sW2_4[i] = W2g[i];
    __syncthreads();

    int w = tid >> 5, lane = tid & 31;
    float* myBuf = sBuf + w * 512;           // 4 rows * 128
    float4 b1v = ((const float4*)b1g)[lane]; // cols 4*lane..4*lane+3

    for (int pass = 0; pass < 2; pass++) {
        int r0 = blockIdx.x * RPB + pass * 32 + w * 4;

        // load 4 agg1 rows into per-warp smem buffer
        #pragma unroll
        for (int i = 0; i < 4; i++) {
            int r = r0 + i;
            float4 a = (r < NN) ? ((const float4*)g_agg1)[r * 32 + lane]
                                : make_float4(0.f, 0.f, 0.f, 0.f);
            ((float4*)myBuf)[i * 32 + lane] = a;
        }
        __syncwarp();

        // GEMM1: acc[i] (cols 4*lane..+3) over k=0..127
        float4 acc0 = make_float4(0, 0, 0, 0), acc1 = acc0, acc2 = acc0, acc3 = acc0;
        const float4* sW1p = (const float4*)sW1;
        #pragma unroll 4
        for (int k = 0; k < F1; k++) {
            float4 wv = sW1p[k * 32 + lane];
            fma4(acc0, myBuf[0 * 128 + k], wv);
            fma4(acc1, myBuf[1 * 128 + k], wv);
            fma4(acc2, myBuf[2 * 128 + k], wv);
            fma4(acc3, myBuf[3 * 128 + k], wv);
        }
        __syncwarp();

        // epilogue1: v = relu(acc*s_in + b1) * s_out -> overwrite buffer
        #pragma unroll
        for (int i = 0; i < 4; i++) {
            int r = r0 + i;
            float si = (r < NN) ? g_sin[r] : 1.0f;
            float so = (r < NN) ? g_sout[r] : 0.0f;
            float4 a = (i == 0) ? acc0 : (i == 1) ? acc1 : (i == 2) ? acc2 : acc3;
            float4 v;
            v.x = fmaxf(fmaf(a.x, si, b1v.x), 0.f) * so;
            v.y = fmaxf(fmaf(a.y, si, b1v.y), 0.f) * so;
            v.z = fmaxf(fmaf(a.z, si, b1v.z), 0.f) * so;
            v.w = fmaxf(fmaf(a.w, si, b1v.w), 0.f) * so;
            ((float4*)myBuf)[i * 32 + lane] = v;
        }
        __syncwarp();

        // GEMM2: cols 2*lane, 2*lane+1 of h2
        float2 c0 = make_float2(0, 0), c1 = c0, c2 = c0, c3 = c0;
        const float2* sW2p = (const float2*)sW2;
        #pragma unroll 4
        for (int k = 0; k < F1; k++) {
            float2 wv = sW2p[k * 32 + lane];
            float a0 = myBuf[0 * 128 + k], a1 = myBuf[1 * 128 + k];
            float a2 = myBuf[2 * 128 + k], a3 = myBuf[3 * 128 + k];
            c0.x = fmaf(a0, wv.x, c0.x); c0.y = fmaf(a0, wv.y, c0.y);
            c1.x = fmaf(a1, wv.x, c1.x); c1.y = fmaf(a1, wv.y, c1.y);
            c2.x = fmaf(a2, wv.x, c2.x); c2.y = fmaf(a2, wv.y, c2.y);
            c3.x = fmaf(a3, wv.x, c3.x); c3.y = fmaf(a3, wv.y, c3.y);
        }

        #pragma unroll
        for (int i = 0; i < 4; i++) {
            int r = r0 + i;
            if (r < NN) {
                float2 c = (i == 0) ? c0 : (i == 1) ? c1 : (i == 2) ? c2 : c3;
                ((float2*)g_h2)[r * 32 + lane] = c;
            }
        }
        __syncwarp();
    }
}

// ---------------- final: y = agg2*s_in + b2; log_softmax; one warp per row ----------------
__global__ void k_out(float* __restrict__ out, const float* __restrict__ b2) {
    int r = (blockIdx.x * blockDim.x + threadIdx.x) >> 5;
    int lane = threadIdx.x & 31;
    if (r >= NN) return;
    float si = g_sin[r];
    float2 b = ((const float2*)b2)[lane];
    float2 a = ((const float2*)g_agg2)[r * 32 + lane];
    float yx = fmaf(a.x, si, b.x);
    float yy = fmaf(a.y, si, b.y);
    float m = fmaxf(yx, yy);
    #pragma unroll
    for (int off = 16; off > 0; off >>= 1)
        m = fmaxf(m, __shfl_xor_sync(0xffffffffu, m, off));
    float s = expf(yx - m) + expf(yy - m);
    #pragma unroll
    for (int off = 16; off > 0; off >>= 1)
        s += __shfl_xor_sync(0xffffffffu, s, off);
    float l = m + logf(s);
    ((float2*)out)[r * 32 + lane] = make_float2(yx - l, yy - l);
}

// ---------------- launch ----------------
extern "C" void kernel_launch(void* const* d_in, const int* in_sizes, int n_in,
                              void* d_out, int out_size) {
    const float* feat = (const float*)d_in[0];
    const int*   src  = (const int*)d_in[1];
    const int*   dst  = (const int*)d_in[2];
    const float* W1   = (const float*)d_in[3];
    const float* b1   = (const float*)d_in[4];
    const float* W2   = (const float*)d_in[5];
    const float* b2   = (const float*)d_in[6];
    float* out = (float*)d_out;

    (void)in_sizes; (void)n_in; (void)out_size;

    static bool attr_done = false;
    const int smem_bytes = (F1 * F1 + F1 * F2 + 8 * 4 * F1) * (int)sizeof(float); // 114688
    if (!attr_done) {
        cudaFuncSetAttribute(k_gemm, cudaFuncAttributeMaxDynamicSharedMemorySize, smem_bytes);
        attr_done = true;
    }

    k_zero_deg<<<(NN + 255) / 256, 256>>>();
    k_deg<<<(NE + 255) / 256, 256>>>(src, dst);
    k_scales<<<(NN + 255) / 256, 256>>>();
    k_prep1<<<(NN * 32 + 255) / 256, 256>>>((const float4*)feat);
    k_zero2<<<(NN * 16 + 255) / 256, 256>>>();
    k_scat1<<<(NE * 32 + 255) / 256, 256>>>(src, dst);
    k_gemm<<<(NN + RPB - 1) / RPB, 256, smem_bytes>>>(
        (const float4*)W1, (const float4*)W2, b1);
    k_scat2<<<(NE * 16 + 255) / 256, 256>>>(src, dst);
    k_out<<<(NN * 32 + 255) / 256, 256>>>(out, b2);
}

// round 4
// speedup vs baseline: 1.4165x; 1.4165x over previous
#include <cuda_runtime.h>

#define NN 50000
#define NE 800000
#define F1 128
#define F2 64
#define NB ((NN + 255) / 256)   // 196 scan blocks

// ---------------- scratch (static device globals) ----------------
__device__ int   g_degout[NN];
__device__ int   g_degin[NN];
__device__ float g_sout[NN];        // rsqrt(clamp(deg_out,1))
__device__ float g_sin[NN];         // rsqrt(clamp(deg_in,1))
__device__ int   g_part[256];       // scan partials (NB<=256)
__device__ int   g_rowstart[NN + 1];
__device__ int   g_cursor[NN];
__device__ int   g_csrc[NE];        // src ids grouped by dst (CSR)
__device__ float g_h2[NN * F2];     // layer-1 output @ W2 (pre-aggregation)

// ---------------- degree + scale ----------------
__global__ void k_zero_deg() {
    int i = blockIdx.x * blockDim.x + threadIdx.x;
    if (i < NN) { g_degout[i] = 0; g_degin[i] = 0; }
}

__global__ void k_deg(const int* __restrict__ src, const int* __restrict__ dst) {
    int e = blockIdx.x * blockDim.x + threadIdx.x;
    if (e < NE) {
        atomicAdd(&g_degout[src[e]], 1);
        atomicAdd(&g_degin[dst[e]], 1);
    }
}

__global__ void k_scales() {
    int i = blockIdx.x * blockDim.x + threadIdx.x;
    if (i < NN) {
        g_sout[i] = rsqrtf(fmaxf((float)g_degout[i], 1.0f));
        g_sin[i]  = rsqrtf(fmaxf((float)g_degin[i], 1.0f));
    }
}

// ---------------- exclusive scan of deg_in -> rowstart (3 kernels) ----------------
__global__ void k_scan1() {
    __shared__ int sh[256];
    int i = blockIdx.x * 256 + threadIdx.x;
    sh[threadIdx.x] = (i < NN) ? g_degin[i] : 0;
    __syncthreads();
    for (int s = 128; s > 0; s >>= 1) {
        if (threadIdx.x < s) sh[threadIdx.x] += sh[threadIdx.x + s];
        __syncthreads();
    }
    if (threadIdx.x == 0) g_part[blockIdx.x] = sh[0];
}

__global__ void k_scan2() {
    __shared__ int sh[256];
    int t = threadIdx.x;
    int v = (t < NB) ? g_part[t] : 0;
    sh[t] = v;
    __syncthreads();
    for (int off = 1; off < 256; off <<= 1) {
        int x = (t >= off) ? sh[t - off] : 0;
        __syncthreads();
        sh[t] += x;
        __syncthreads();
    }
    g_part[t] = sh[t] - v;                 // exclusive
    if (t == 255) g_rowstart[NN] = sh[255]; // total = NE
}

__global__ void k_scan3() {
    __shared__ int sh[256];
    int t = threadIdx.x;
    int i = blockIdx.x * 256 + t;
    int v = (i < NN) ? g_degin[i] : 0;
    sh[t] = v;
    __syncthreads();
    for (int off = 1; off < 256; off <<= 1) {
        int x = (t >= off) ? sh[t - off] : 0;
        __syncthreads();
        sh[t] += x;
        __syncthreads();
    }
    if (i < NN) {
        g_rowstart[i] = g_part[blockIdx.x] + sh[t] - v;
        g_cursor[i] = 0;
    }
}

__global__ void k_fill(const int* __restrict__ src, const int* __restrict__ dst) {
    int e = blockIdx.x * 256 + threadIdx.x;
    if (e < NE) {
        int d = dst[e];
        int p = atomicAdd(&g_cursor[d], 1);
        g_csrc[g_rowstart[d] + p] = src[e];
    }
}

// ---------------- fused: gather1 + GEMM1 + relu + GEMM2 ----------------
// per row r: agg = sum_{s in N(r)} feat[s]*sout[s]        (gather, registers)
//            v   = relu(agg@W1 * sin[r] + b1) * sout[r]
//            h2[r] = v @ W2
#define RPB 64  // rows per block: 8 warps * 4 rows * 2 passes

__device__ __forceinline__ void fma4(float4& acc, float a, const float4& w) {
    acc.x = fmaf(a, w.x, acc.x);
    acc.y = fmaf(a, w.y, acc.y);
    acc.z = fmaf(a, w.z, acc.z);
    acc.w = fmaf(a, w.w, acc.w);
}

__global__ __launch_bounds__(256, 2)
void k_fused(const float4* __restrict__ feat4, const float4* __restrict__ W1g,
             const float4* __restrict__ W2g, const float* __restrict__ b1g) {
    extern __shared__ float sm[];
    float* sW1 = sm;                       // 16384 floats
    float* sW2 = sm + F1 * F1;             // 8192 floats
    float* sBuf = sW2 + F1 * F2;           // 8 warps * 512 floats

    int tid = threadIdx.x;
    #pragma unroll 4
    for (int i = tid; i < (F1 * F1) / 4; i += 256) ((float4*)sW1)[i] = W1g[i];
    #pragma unroll 2
    for (int i = tid; i < (F1 * F2) / 4; i += 256) ((float4*)sW2)[i] = W2g[i];
    __syncthreads();

    int w = tid >> 5, lane = tid & 31;
    float* myBuf = sBuf + w * 512;
    float4 b1v = ((const float4*)b1g)[lane];

    for (int pass = 0; pass < 2; pass++) {
        int r0 = blockIdx.x * RPB + pass * 32 + w * 4;

        // ---- gather 4 rows from feat via CSR (register accumulation) ----
        #pragma unroll
        for (int i = 0; i < 4; i++) {
            int r = r0 + i;
            float4 acc = make_float4(0.f, 0.f, 0.f, 0.f);
            if (r < NN) {
                int beg = g_rowstart[r], end = g_rowstart[r + 1];
                for (int j = beg; j < end; j += 32) {
                    int n = min(32, end - j);
                    int sid = 0; float sv = 0.f;
                    if (lane < n) { sid = g_csrc[j + lane]; sv = g_sout[sid]; }
                    for (int kk = 0; kk < n; kk++) {
                        int   s  = __shfl_sync(0xffffffffu, sid, kk);
                        float sc = __shfl_sync(0xffffffffu, sv, kk);
                        float4 f = feat4[s * 32 + lane];
                        fma4(acc, sc, f);
                    }
                }
            }
            ((float4*)myBuf)[i * 32 + lane] = acc;
        }
        __syncwarp();

        // ---- GEMM1: out cols 4*lane..+3, k = 0..127 ----
        float4 acc0 = make_float4(0, 0, 0, 0), acc1 = acc0, acc2 = acc0, acc3 = acc0;
        const float4* sW1p = (const float4*)sW1;
        #pragma unroll 4
        for (int k = 0; k < F1; k++) {
            float4 wv = sW1p[k * 32 + lane];
            fma4(acc0, myBuf[0 * 128 + k], wv);
            fma4(acc1, myBuf[1 * 128 + k], wv);
            fma4(acc2, myBuf[2 * 128 + k], wv);
            fma4(acc3, myBuf[3 * 128 + k], wv);
        }
        __syncwarp();

        // ---- epilogue1: v = relu(acc*s_in + b1) * s_out ----
        #pragma unroll
        for (int i = 0; i < 4; i++) {
            int r = r0 + i;
            float si = (r < NN) ? g_sin[r] : 1.0f;
            float so = (r < NN) ? g_sout[r] : 0.0f;
            float4 a = (i == 0) ? acc0 : (i == 1) ? acc1 : (i == 2) ? acc2 : acc3;
            float4 v;
            v.x = fmaxf(fmaf(a.x, si, b1v.x), 0.f) * so;
            v.y = fmaxf(fmaf(a.y, si, b1v.y), 0.f) * so;
            v.z = fmaxf(fmaf(a.z, si, b1v.z), 0.f) * so;
            v.w = fmaxf(fmaf(a.w, si, b1v.w), 0.f) * so;
            ((float4*)myBuf)[i * 32 + lane] = v;
        }
        __syncwarp();

        // ---- GEMM2: out cols 2*lane, 2*lane+1 ----
        float2 c0 = make_float2(0, 0), c1 = c0, c2 = c0, c3 = c0;
        const float2* sW2p = (const float2*)sW2;
        #pragma unroll 4
        for (int k = 0; k < F1; k++) {
            float2 wv = sW2p[k * 32 + lane];
            float a0 = myBuf[0 * 128 + k], a1 = myBuf[1 * 128 + k];
            float a2 = myBuf[2 * 128 + k], a3 = myBuf[3 * 128 + k];
            c0.x = fmaf(a0, wv.x, c0.x); c0.y = fmaf(a0, wv.y, c0.y);
            c1.x = fmaf(a1, wv.x, c1.x); c1.y = fmaf(a1, wv.y, c1.y);
            c2.x = fmaf(a2, wv.x, c2.x); c2.y = fmaf(a2, wv.y, c2.y);
            c3.x = fmaf(a3, wv.x, c3.x); c3.y = fmaf(a3, wv.y, c3.y);
        }

        #pragma unroll
        for (int i = 0; i < 4; i++) {
            int r = r0 + i;
            if (r < NN) {
                float2 c = (i == 0) ? c0 : (i == 1) ? c1 : (i == 2) ? c2 : c3;
                ((float2*)g_h2)[r * 32 + lane] = c;
            }
        }
        __syncwarp();
    }
}

// ---------------- fused: gather2 + bias + log_softmax (warp per node) ----------------
__global__ void k_layer2(float* __restrict__ out, const float* __restrict__ b2) {
    int r = (blockIdx.x * blockDim.x + threadIdx.x) >> 5;
    int lane = threadIdx.x & 31;
    if (r >= NN) return;

    int beg = g_rowstart[r], end = g_rowstart[r + 1];
    float2 acc = make_float2(0.f, 0.f);
    for (int j = beg; j < end; j += 32) {
        int n = min(32, end - j);
        int sid = (lane < n) ? g_csrc[j + lane] : 0;
        for (int kk = 0; kk < n; kk++) {
            int s = __shfl_sync(0xffffffffu, sid, kk);
            float2 h = ((const float2*)g_h2)[s * 32 + lane];
            acc.x += h.x;
            acc.y += h.y;
        }
    }

    float si = g_sin[r];
    float2 b = ((const float2*)b2)[lane];
    float yx = fmaf(acc.x, si, b.x);
    float yy = fmaf(acc.y, si, b.y);

    float m = fmaxf(yx, yy);
    #pragma unroll
    for (int off = 16; off > 0; off >>= 1)
        m = fmaxf(m, __shfl_xor_sync(0xffffffffu, m, off));
    float ssum = expf(yx - m) + expf(yy - m);
    #pragma unroll
    for (int off = 16; off > 0; off >>= 1)
        ssum += __shfl_xor_sync(0xffffffffu, ssum, off);
    float l = m + logf(ssum);

    ((float2*)out)[r * 32 + lane] = make_float2(yx - l, yy - l);
}

// ---------------- launch ----------------
extern "C" void kernel_launch(void* const* d_in, const int* in_sizes, int n_in,
                              void* d_out, int out_size) {
    const float* feat = (const float*)d_in[0];
    const int*   src  = (const int*)d_in[1];
    const int*   dst  = (const int*)d_in[2];
    const float* W1   = (const float*)d_in[3];
    const float* b1   = (const float*)d_in[4];
    const float* W2   = (const float*)d_in[5];
    const float* b2   = (const float*)d_in[6];
    float* out = (float*)d_out;

    (void)in_sizes; (void)n_in; (void)out_size;

    static bool attr_done = false;
    const int smem_bytes = (F1 * F1 + F1 * F2 + 8 * 4 * F1) * (int)sizeof(float); // 114688
    if (!attr_done) {
        cudaFuncSetAttribute(k_fused, cudaFuncAttributeMaxDynamicSharedMemorySize, smem_bytes);
        attr_done = true;
    }

    k_zero_deg<<<NB, 256>>>();
    k_deg<<<(NE + 255) / 256, 256>>>(src, dst);
    k_scales<<<NB, 256>>>();
    k_scan1<<<NB, 256>>>();
    k_scan2<<<1, 256>>>();
    k_scan3<<<NB, 256>>>();
    k_fill<<<(NE + 255) / 256, 256>>>(src, dst);
    k_fused<<<(NN + RPB - 1) / RPB, 256, smem_bytes>>>(
        (const float4*)feat, (const float4*)W1, (const float4*)W2, b1);
    k_layer2<<<(NN * 32 + 255) / 256, 256>>>(out, b2);
}

// round 7
// speedup vs baseline: 1.4289x; 1.0088x over previous
#include <cuda_runtime.h>

#define NN 50000
#define NE 800000
#define F1 128
#define F2 64
#define NB ((NN + 255) / 256)   // 196 scan blocks

typedef unsigned long long u64t;

// ---------------- packed f32x2 helpers (Blackwell FFMA2 path) ----------------
__device__ __forceinline__ u64t pack2(float a, float b) {
    u64t r; asm("mov.b64 %0,{%1,%2};" : "=l"(r) : "f"(a), "f"(b)); return r;
}
__device__ __forceinline__ float2 unpack2(u64t v) {
    float2 r; asm("mov.b64 {%0,%1},%2;" : "=f"(r.x), "=f"(r.y) : "l"(v)); return r;
}
__device__ __forceinline__ void ffma2(u64t& d, u64t a, u64t b) {
    asm("fma.rn.f32x2 %0,%1,%2,%0;" : "+l"(d) : "l"(a), "l"(b));
}
__device__ __forceinline__ void fadd2(u64t& d, u64t a) {
    asm("add.rn.f32x2 %0,%0,%1;" : "+l"(d) : "l"(a));
}

// ---------------- scratch (static device globals) ----------------
__device__ int   g_degout[NN];
__device__ int   g_degin[NN];
__device__ float g_sout[NN];
__device__ float g_sin[NN];
__device__ int   g_part[256];
__device__ int   g_rowstart[NN + 1];
__device__ int   g_cursor[NN];
__device__ int   g_csrc[NE];
__device__ float g_h2[NN * F2];

// ---------------- degree ----------------
__global__ void k_zero_deg() {
    int i = blockIdx.x * blockDim.x + threadIdx.x;
    if (i < NN) { g_degout[i] = 0; g_degin[i] = 0; }
}

__global__ void k_deg(const int* __restrict__ src, const int* __restrict__ dst) {
    int e = blockIdx.x * blockDim.x + threadIdx.x;
    if (e < NE) {
        atomicAdd(&g_degout[src[e]], 1);
        atomicAdd(&g_degin[dst[e]], 1);
    }
}

// ---------------- scan1 (+ fused scale computation) ----------------
__global__ void k_scan1() {
    __shared__ int sh[256];
    int i = blockIdx.x * 256 + threadIdx.x;
    int din = 0;
    if (i < NN) {
        din = g_degin[i];
        g_sout[i] = rsqrtf(fmaxf((float)g_degout[i], 1.0f));
        g_sin[i]  = rsqrtf(fmaxf((float)din, 1.0f));
    }
    sh[threadIdx.x] = din;
    __syncthreads();
    for (int s = 128; s > 0; s >>= 1) {
        if (threadIdx.x < s) sh[threadIdx.x] += sh[threadIdx.x + s];
        __syncthreads();
    }
    if (threadIdx.x == 0) g_part[blockIdx.x] = sh[0];
}

__global__ void k_scan2() {
    __shared__ int sh[256];
    int t = threadIdx.x;
    int v = (t < NB) ? g_part[t] : 0;
    sh[t] = v;
    __syncthreads();
    for (int off = 1; off < 256; off <<= 1) {
        int x = (t >= off) ? sh[t - off] : 0;
        __syncthreads();
        sh[t] += x;
        __syncthreads();
    }
    g_part[t] = sh[t] - v;
    if (t == 255) g_rowstart[NN] = sh[255];
}

__global__ void k_scan3() {
    __shared__ int sh[256];
    int t = threadIdx.x;
    int i = blockIdx.x * 256 + t;
    int v = (i < NN) ? g_degin[i] : 0;
    sh[t] = v;
    __syncthreads();
    for (int off = 1; off < 256; off <<= 1) {
        int x = (t >= off) ? sh[t - off] : 0;
        __syncthreads();
        sh[t] += x;
        __syncthreads();
    }
    if (i < NN) {
        g_rowstart[i] = g_part[blockIdx.x] + sh[t] - v;
        g_cursor[i] = 0;
    }
}

__global__ void k_fill(const int* __restrict__ src, const int* __restrict__ dst) {
    int e = blockIdx.x * 256 + threadIdx.x;
    if (e < NE) {
        int d = dst[e];
        int p = atomicAdd(&g_cursor[d], 1);
        g_csrc[g_rowstart[d] + p] = src[e];
    }
}

// ---------------- fused: gather1 + GEMM1 + relu + GEMM2 (FFMA2) ----------------
#define RPB 64  // 8 warps * 4 rows * 2 passes

__global__ __launch_bounds__(256, 2)
void k_fused(const float* __restrict__ featp, const float4* __restrict__ W1g,
             const float4* __restrict__ W2g, const float* __restrict__ b1g) {
    extern __shared__ float sm[];
    float* sW1 = sm;                       // 16384 floats
    float* sW2 = sm + F1 * F1;             // 8192 floats
    float* sBuf = sW2 + F1 * F2;           // 8 warps * 512 floats

    int tid = threadIdx.x;
    #pragma unroll 4
    for (int i = tid; i < (F1 * F1) / 4; i += 256) ((float4*)sW1)[i] = W1g[i];
    #pragma unroll 2
    for (int i = tid; i < (F1 * F2) / 4; i += 256) ((float4*)sW2)[i] = W2g[i];
    __syncthreads();

    int w = tid >> 5, lane = tid & 31;
    float* myBuf = sBuf + w * 512;
    float4 b1v = ((const float4*)b1g)[lane];
    const longlong2* feat2 = (const longlong2*)featp;
    const longlong2* sW1ll = (const longlong2*)sW1;
    const u64t*      sW2ll = (const u64t*)sW2;

    for (int pass = 0; pass < 2; pass++) {
        int r0 = blockIdx.x * RPB + pass * 32 + w * 4;

        // ---- gather 4 rows from feat via CSR (packed accumulation) ----
        #pragma unroll
        for (int i = 0; i < 4; i++) {
            int r = r0 + i;
            u64t acc0 = 0, acc1 = 0;
            if (r < NN) {
                int beg = g_rowstart[r], end = g_rowstart[r + 1];
                for (int j = beg; j < end; j += 32) {
                    int n = min(32, end - j);
                    int sid = 0; float sv = 0.f;
                    if (lane < n) { sid = g_csrc[j + lane]; sv = g_sout[sid]; }
                    #pragma unroll 4
                    for (int kk = 0; kk < n; kk++) {
                        int   s  = __shfl_sync(0xffffffffu, sid, kk);
                        float sc = __shfl_sync(0xffffffffu, sv, kk);
                        longlong2 f = feat2[s * 32 + lane];
                        u64t sp = pack2(sc, sc);
                        ffma2(acc0, sp, (u64t)f.x);
                        ffma2(acc1, sp, (u64t)f.y);
                    }
                }
            }
            float2 a0 = unpack2(acc0), a1 = unpack2(acc1);
            ((float4*)myBuf)[i * 32 + lane] = make_float4(a0.x, a0.y, a1.x, a1.y);
        }
        __syncwarp();

        // ---- GEMM1 (FFMA2): out cols 4*lane..+3, k = 0..127 ----
        u64t g00 = 0, g01 = 0, g10 = 0, g11 = 0, g20 = 0, g21 = 0, g30 = 0, g31 = 0;
        #pragma unroll 4
        for (int k = 0; k < F1; k++) {
            longlong2 wv = sW1ll[k * 32 + lane];
            float a0 = myBuf[0 * 128 + k], a1 = myBuf[1 * 128 + k];
            float a2 = myBuf[2 * 128 + k], a3 = myBuf[3 * 128 + k];
            u64t p0 = pack2(a0, a0), p1 = pack2(a1, a1);
            u64t p2 = pack2(a2, a2), p3 = pack2(a3, a3);
            ffma2(g00, p0, (u64t)wv.x); ffma2(g01, p0, (u64t)wv.y);
            ffma2(g10, p1, (u64t)wv.x); ffma2(g11, p1, (u64t)wv.y);
            ffma2(g20, p2, (u64t)wv.x); ffma2(g21, p2, (u64t)wv.y);
            ffma2(g30, p3, (u64t)wv.x); ffma2(g31, p3, (u64t)wv.y);
        }
        __syncwarp();

        // ---- epilogue1: v = relu(acc*s_in + b1) * s_out ----
        #pragma unroll
        for (int i = 0; i < 4; i++) {
            int r = r0 + i;
            float si = (r < NN) ? g_sin[r] : 1.0f;
            float so = (r < NN) ? g_sout[r] : 0.0f;
            float2 lo = unpack2(i == 0 ? g00 : i == 1 ? g10 : i == 2 ? g20 : g30);
            float2 hi = unpack2(i == 0 ? g01 : i == 1 ? g11 : i == 2 ? g21 : g31);
            float4 v;
            v.x = fmaxf(fmaf(lo.x, si, b1v.x), 0.f) * so;
            v.y = fmaxf(fmaf(lo.y, si, b1v.y), 0.f) * so;
            v.z = fmaxf(fmaf(hi.x, si, b1v.z), 0.f) * so;
            v.w = fmaxf(fmaf(hi.y, si, b1v.w), 0.f) * so;
            ((float4*)myBuf)[i * 32 + lane] = v;
        }
        __syncwarp();

        // ---- GEMM2 (FFMA2): out cols 2*lane, 2*lane+1 ----
        u64t c0 = 0, c1 = 0, c2 = 0, c3 = 0;
        #pragma unroll 4
        for (int k = 0; k < F1; k++) {
            u64t wv = sW2ll[k * 32 + lane];
            float a0 = myBuf[0 * 128 + k], a1 = myBuf[1 * 128 + k];
            float a2 = myBuf[2 * 128 + k], a3 = myBuf[3 * 128 + k];
            ffma2(c0, pack2(a0, a0), wv);
            ffma2(c1, pack2(a1, a1), wv);
            ffma2(c2, pack2(a2, a2), wv);
            ffma2(c3, pack2(a3, a3), wv);
        }

        #pragma unroll
        for (int i = 0; i < 4; i++) {
            int r = r0 + i;
            if (r < NN) {
                float2 c = unpack2(i == 0 ? c0 : i == 1 ? c1 : i == 2 ? c2 : c3);
                ((float2*)g_h2)[r * 32 + lane] = c;
            }
        }
        __syncwarp();
    }
}

// ---------------- fused: gather2 + bias + log_softmax (warp per node) ----------------
__global__ void k_layer2(float* __restrict__ out, const float* __restrict__ b2) {
    int r = (blockIdx.x * blockDim.x + threadIdx.x) >> 5;
    int lane = threadIdx.x & 31;
    if (r >= NN) return;

    int beg = g_rowstart[r], end = g_rowstart[r + 1];
    u64t acc = 0;
    const u64t* h2ll = (const u64t*)g_h2;
    for (int j = beg; j < end; j += 32) {
        int n = min(32, end - j);
        int sid = (lane < n) ? g_csrc[j + lane] : 0;
        #pragma unroll 4
        for (int kk = 0; kk < n; kk++) {
            int s = __shfl_sync(0xffffffffu, sid, kk);
            fadd2(acc, h2ll[s * 32 + lane]);
        }
    }

    float si = g_sin[r];
    float2 a = unpack2(acc);
    float2 b = ((const float2*)b2)[lane];
    float yx = fmaf(a.x, si, b.x);
    float yy = fmaf(a.y, si, b.y);

    float m = fmaxf(yx, yy);
    #pragma unroll
    for (int off = 16; off > 0; off >>= 1)
        m = fmaxf(m, __shfl_xor_sync(0xffffffffu, m, off));
    float ssum = expf(yx - m) + expf(yy - m);
    #pragma unroll
    for (int off = 16; off > 0; off >>= 1)
        ssum += __shfl_xor_sync(0xffffffffu, ssum, off);
    float l = m + logf(ssum);

    ((float2*)out)[r * 32 + lane] = make_float2(yx - l, yy - l);
}

// ---------------- launch ----------------
extern "C" void kernel_launch(void* const* d_in, const int* in_sizes, int n_in,
                              void* d_out, int out_size) {
    const float* feat = (const float*)d_in[0];
    const int*   src  = (const int*)d_in[1];
    const int*   dst  = (const int*)d_in[2];
    const float* W1   = (const float*)d_in[3];
    const float* b1   = (const float*)d_in[4];
    const float* W2   = (const float*)d_in[5];
    const float* b2   = (const float*)d_in[6];
    float* out = (float*)d_out;

    (void)in_sizes; (void)n_in; (void)out_size;

    static bool attr_done = false;
    const int smem_bytes = (F1 * F1 + F1 * F2 + 8 * 4 * F1) * (int)sizeof(float); // 114688
    if (!attr_done) {
        cudaFuncSetAttribute(k_fused, cudaFuncAttributeMaxDynamicSharedMemorySize, smem_bytes);
        attr_done = true;
    }

    k_zero_deg<<<NB, 256>>>();
    k_deg<<<(NE + 255) / 256, 256>>>(src, dst);
    k_scan1<<<NB, 256>>>();
    k_scan2<<<1, 256>>>();
    k_scan3<<<NB, 256>>>();
    k_fill<<<(NE + 255) / 256, 256>>>(src, dst);
    k_fused<<<(NN + RPB - 1) / RPB, 256, smem_bytes>>>(
        feat, (const float4*)W1, (const float4*)W2, b1);
    k_layer2<<<(NN * 32 + 255) / 256, 256>>>(out, b2);
}

// round 10
// speedup vs baseline: 1.4848x; 1.0391x over previous
#include <cuda_runtime.h>

#define NN 50000
#define NE 800000
#define F1 128
#define F2 64
#define NB ((NN + 255) / 256)   // 196 scan blocks

typedef unsigned long long u64t;

// ---------------- packed f32x2 helpers ----------------
__device__ __forceinline__ u64t pack2(float a, float b) {
    u64t r; asm("mov.b64 %0,{%1,%2};" : "=l"(r) : "f"(a), "f"(b)); return r;
}
__device__ __forceinline__ float2 unpack2(u64t v) {
    float2 r; asm("mov.b64 {%0,%1},%2;" : "=f"(r.x), "=f"(r.y) : "l"(v)); return r;
}
__device__ __forceinline__ void ffma2(u64t& d, u64t a, u64t b) {
    asm("fma.rn.f32x2 %0,%1,%2,%0;" : "+l"(d) : "l"(a), "l"(b));
}
__device__ __forceinline__ void fadd2(u64t& d, u64t a) {
    asm("add.rn.f32x2 %0,%0,%1;" : "+l"(d) : "l"(a));
}

// ---------------- scratch ----------------
__device__ int   g_degout[NN];
__device__ int   g_degin[NN];
__device__ float g_sout[NN];
__device__ float g_sin[NN];
__device__ int   g_part[256];
__device__ int   g_rowstart[NN + 1];
__device__ int   g_cursor[NN];
__device__ int   g_csrc[NE];
__device__ float g_h2[NN * F2];

// ---------------- degree (vectorized) ----------------
__global__ void k_zero_deg() {
    int i = blockIdx.x * blockDim.x + threadIdx.x;   // NN/4 = 12500 int4 slots
    if (i < NN / 4) {
        ((int4*)g_degout)[i] = make_int4(0, 0, 0, 0);
        ((int4*)g_degin)[i]  = make_int4(0, 0, 0, 0);
    }
}

__global__ void k_deg(const int4* __restrict__ src4, const int4* __restrict__ dst4) {
    int i = blockIdx.x * blockDim.x + threadIdx.x;   // NE/4 = 200000
    if (i < NE / 4) {
        int4 s = src4[i], d = dst4[i];
        atomicAdd(&g_degout[s.x], 1); atomicAdd(&g_degout[s.y], 1);
        atomicAdd(&g_degout[s.z], 1); atomicAdd(&g_degout[s.w], 1);
        atomicAdd(&g_degin[d.x], 1);  atomicAdd(&g_degin[d.y], 1);
        atomicAdd(&g_degin[d.z], 1);  atomicAdd(&g_degin[d.w], 1);
    }
}

// ---------------- scan1 (+ fused scale computation) ----------------
__global__ void k_scan1() {
    __shared__ int sh[256];
    int i = blockIdx.x * 256 + threadIdx.x;
    int din = 0;
    if (i < NN) {
        din = g_degin[i];
        g_sout[i] = rsqrtf(fmaxf((float)g_degout[i], 1.0f));
        g_sin[i]  = rsqrtf(fmaxf((float)din, 1.0f));
    }
    sh[threadIdx.x] = din;
    __syncthreads();
    for (int s = 128; s > 0; s >>= 1) {
        if (threadIdx.x < s) sh[threadIdx.x] += sh[threadIdx.x + s];
        __syncthreads();
    }
    if (threadIdx.x == 0) g_part[blockIdx.x] = sh[0];
}

__global__ void k_scan2() {
    __shared__ int sh[256];
    int t = threadIdx.x;
    int v = (t < NB) ? g_part[t] : 0;
    sh[t] = v;
    __syncthreads();
    for (int off = 1; off < 256; off <<= 1) {
        int x = (t >= off) ? sh[t - off] : 0;
        __syncthreads();
        sh[t] += x;
        __syncthreads();
    }
    g_part[t] = sh[t] - v;
    if (t == 255) g_rowstart[NN] = sh[255];
}

__global__ void k_scan3() {
    __shared__ int sh[256];
    int t = threadIdx.x;
    int i = blockIdx.x * 256 + t;
    int v = (i < NN) ? g_degin[i] : 0;
    sh[t] = v;
    __syncthreads();
    for (int off = 1; off < 256; off <<= 1) {
        int x = (t >= off) ? sh[t - off] : 0;
        __syncthreads();
        sh[t] += x;
        __syncthreads();
    }
    if (i < NN) {
        g_rowstart[i] = g_part[blockIdx.x] + sh[t] - v;
        g_cursor[i] = 0;
    }
}

__global__ void k_fill(const int4* __restrict__ src4, const int4* __restrict__ dst4) {
    int i = blockIdx.x * blockDim.x + threadIdx.x;
    if (i < NE / 4) {
        int4 s = src4[i], d = dst4[i];
        int p;
        p = atomicAdd(&g_cursor[d.x], 1); g_csrc[g_rowstart[d.x] + p] = s.x;
        p = atomicAdd(&g_cursor[d.y], 1); g_csrc[g_rowstart[d.y] + p] = s.y;
        p = atomicAdd(&g_cursor[d.z], 1); g_csrc[g_rowstart[d.z] + p] = s.z;
        p = atomicAdd(&g_cursor[d.w], 1); g_csrc[g_rowstart[d.w] + p] = s.w;
    }
}

// ---------------- fused: gather1 + GEMM1 + relu + GEMM2 ----------------
#define RPB 64  // 8 warps * 4 rows * 2 passes

__global__ __launch_bounds__(256, 2)
void k_fused(const float* __restrict__ featp, const float4* __restrict__ W1g,
             const float4* __restrict__ W2g, const float* __restrict__ b1g) {
    extern __shared__ float sm[];
    float* sW1 = sm;                       // 16384 floats
    float* sW2 = sm + F1 * F1;             // 8192 floats
    float* sBuf = sW2 + F1 * F2;           // 8 warps * 512 floats

    int tid = threadIdx.x;
    #pragma unroll 4
    for (int i = tid; i < (F1 * F1) / 4; i += 256) ((float4*)sW1)[i] = W1g[i];
    #pragma unroll 2
    for (int i = tid; i < (F1 * F2) / 4; i += 256) ((float4*)sW2)[i] = W2g[i];
    __syncthreads();

    int w = tid >> 5, lane = tid & 31;
    float* myBuf = sBuf + w * 512;
    float4 b1v = ((const float4*)b1g)[lane];
    const longlong2* feat2 = (const longlong2*)featp;
    const longlong2* sW1ll = (const longlong2*)sW1;
    const u64t*      sW2ll = (const u64t*)sW2;

    for (int pass = 0; pass < 2; pass++) {
        int r0 = blockIdx.x * RPB + pass * 32 + w * 4;

        // ---- gather 4 rows from feat via CSR (manual MLP batching) ----
        #pragma unroll
        for (int i = 0; i < 4; i++) {
            int r = r0 + i;
            u64t acc0 = 0, acc1 = 0;
            if (r < NN) {
                int beg = __ldg(&g_rowstart[r]), end = __ldg(&g_rowstart[r + 1]);
                for (int j = beg; j < end; j += 32) {
                    int n = min(32, end - j);
                    int sid = 0; float sv = 0.f;
                    if (lane < n) { sid = g_csrc[j + lane]; sv = g_sout[sid]; }
                    int kk = 0;
                    // 8-edge batches: 8 independent loads in flight
                    for (; kk + 8 <= n; kk += 8) {
                        longlong2 f[8]; u64t sp[8];
                        #pragma unroll
                        for (int q = 0; q < 8; q++) {
                            int   s  = __shfl_sync(0xffffffffu, sid, kk + q);
                            float sc = __shfl_sync(0xffffffffu, sv, kk + q);
                            f[q] = feat2[s * 32 + lane];
                            sp[q] = pack2(sc, sc);
                        }
                        #pragma unroll
                        for (int q = 0; q < 8; q++) {
                            ffma2(acc0, sp[q], (u64t)f[q].x);
                            ffma2(acc1, sp[q], (u64t)f[q].y);
                        }
                    }
                    for (; kk < n; kk++) {
                        int   s  = __shfl_sync(0xffffffffu, sid, kk);
                        float sc = __shfl_sync(0xffffffffu, sv, kk);
                        longlong2 f = feat2[s * 32 + lane];
                        u64t sp = pack2(sc, sc);
                        ffma2(acc0, sp, (u64t)f.x);
                        ffma2(acc1, sp, (u64t)f.y);
                    }
                }
            }
            float2 a0 = unpack2(acc0), a1 = unpack2(acc1);
            ((float4*)myBuf)[i * 32 + lane] = make_float4(a0.x, a0.y, a1.x, a1.y);
        }
        __syncwarp();

        // ---- GEMM1 (FFMA2) ----
        u64t g00 = 0, g01 = 0, g10 = 0, g11 = 0, g20 = 0, g21 = 0, g30 = 0, g31 = 0;
        #pragma unroll 4
        for (int k = 0; k < F1; k++) {
            longlong2 wv = sW1ll[k * 32 + lane];
            float a0 = myBuf[0 * 128 + k], a1 = myBuf[1 * 128 + k];
            float a2 = myBuf[2 * 128 + k], a3 = myBuf[3 * 128 + k];
            u64t p0 = pack2(a0, a0), p1 = pack2(a1, a1);
            u64t p2 = pack2(a2, a2), p3 = pack2(a3, a3);
            ffma2(g00, p0, (u64t)wv.x); ffma2(g01, p0, (u64t)wv.y);
            ffma2(g10, p1, (u64t)wv.x); ffma2(g11, p1, (u64t)wv.y);
            ffma2(g20, p2, (u64t)wv.x); ffma2(g21, p2, (u64t)wv.y);
            ffma2(g30, p3, (u64t)wv.x); ffma2(g31, p3, (u64t)wv.y);
        }
        __syncwarp();

        // ---- epilogue1: v = relu(acc*s_in + b1) * s_out ----
        #pragma unroll
        for (int i = 0; i < 4; i++) {
            int r = r0 + i;
            float si = (r < NN) ? g_sin[r] : 1.0f;
            float so = (r < NN) ? g_sout[r] : 0.0f;
            float2 lo = unpack2(i == 0 ? g00 : i == 1 ? g10 : i == 2 ? g20 : g30);
            float2 hi = unpack2(i == 0 ? g01 : i == 1 ? g11 : i == 2 ? g21 : g31);
            float4 v;
            v.x = fmaxf(fmaf(lo.x, si, b1v.x), 0.f) * so;
            v.y = fmaxf(fmaf(lo.y, si, b1v.y), 0.f) * so;
            v.z = fmaxf(fmaf(hi.x, si, b1v.z), 0.f) * so;
            v.w = fmaxf(fmaf(hi.y, si, b1v.w), 0.f) * so;
            ((float4*)myBuf)[i * 32 + lane] = v;
        }
        __syncwarp();

        // ---- GEMM2 (FFMA2) ----
        u64t c0 = 0, c1 = 0, c2 = 0, c3 = 0;
        #pragma unroll 4
        for (int k = 0; k < F1; k++) {
            u64t wv = sW2ll[k * 32 + lane];
            float a0 = myBuf[0 * 128 + k], a1 = myBuf[1 * 128 + k];
            float a2 = myBuf[2 * 128 + k], a3 = myBuf[3 * 128 + k];
            ffma2(c0, pack2(a0, a0), wv);
            ffma2(c1, pack2(a1, a1), wv);
            ffma2(c2, pack2(a2, a2), wv);
            ffma2(c3, pack2(a3, a3), wv);
        }

        #pragma unroll
        for (int i = 0; i < 4; i++) {
            int r = r0 + i;
            if (r < NN) {
                float2 c = unpack2(i == 0 ? c0 : i == 1 ? c1 : i == 2 ? c2 : c3);
                ((float2*)g_h2)[r * 32 + lane] = c;
            }
        }
        __syncwarp();
    }
}

// ---------------- fused: gather2 + bias + log_softmax ----------------
// 2 nodes per warp; 16-lane groups; float4 per lane (16*16B = one h2 row).
__global__ void k_layer2(float* __restrict__ out, const float* __restrict__ b2) {
    int t = blockIdx.x * blockDim.x + threadIdx.x;
    int warp = t >> 5;
    int lane = threadIdx.x & 31;
    int g = lane >> 4;          // group 0/1
    int sub = lane & 15;
    int r = warp * 2 + g;
    if (r >= NN) return;
    unsigned gmask = 0xFFFFu << (g * 16);

    int beg = __ldg(&g_rowstart[r]), end = __ldg(&g_rowstart[r + 1]);
    u64t acc0 = 0, acc1 = 0;
    const longlong2* h2v = (const longlong2*)g_h2;
    for (int j = beg; j < end; j += 16) {
        int n = min(16, end - j);
        int sid = (sub < n) ? g_csrc[j + sub] : 0;
        int kk = 0;
        for (; kk + 4 <= n; kk += 4) {
            longlong2 f[4];
            #pragma unroll
            for (int q = 0; q < 4; q++) {
                int s = __shfl_sync(gmask, sid, kk + q, 16);
                f[q] = h2v[s * 16 + sub];
            }
            #pragma unroll
            for (int q = 0; q < 4; q++) {
                fadd2(acc0, (u64t)f[q].x);
                fadd2(acc1, (u64t)f[q].y);
            }
        }
        for (; kk < n; kk++) {
            int s = __shfl_sync(gmask, sid, kk, 16);
            longlong2 f = h2v[s * 16 + sub];
            fadd2(acc0, (u64t)f.x);
            fadd2(acc1, (u64t)f.y);
        }
    }

    float si = g_sin[r];
    float2 a0 = unpack2(acc0), a1 = unpack2(acc1);
    float4 b = ((const float4*)b2)[sub];
    float y0 = fmaf(a0.x, si, b.x);
    float y1 = fmaf(a0.y, si, b.y);
    float y2 = fmaf(a1.x, si, b.z);
    float y3 = fmaf(a1.y, si, b.w);

    float m = fmaxf(fmaxf(y0, y1), fmaxf(y2, y3));
    #pragma unroll
    for (int off = 8; off > 0; off >>= 1)
        m = fmaxf(m, __shfl_xor_sync(gmask, m, off, 16));
    float ssum = expf(y0 - m) + expf(y1 - m) + expf(y2 - m) + expf(y3 - m);
    #pragma unroll
    for (int off = 8; off > 0; off >>= 1)
        ssum += __shfl_xor_sync(gmask, ssum, off, 16);
    float l = m + logf(ssum);

    ((float4*)out)[r * 16 + sub] = make_float4(y0 - l, y1 - l, y2 - l, y3 - l);
}

// ---------------- launch ----------------
extern "C" void kernel_launch(void* const* d_in, const int* in_sizes, int n_in,
                              void* d_out, int out_size) {
    const float* feat = (const float*)d_in[0];
    const int*   src  = (const int*)d_in[1];
    const int*   dst  = (const int*)d_in[2];
    const float* W1   = (const float*)d_in[3];
    const float* b1   = (const float*)d_in[4];
    const float* W2   = (const float*)d_in[5];
    const float* b2   = (const float*)d_in[6];
    float* out = (float*)d_out;

    (void)in_sizes; (void)n_in; (void)out_size;

    static bool attr_done = false;
    const int smem_bytes = (F1 * F1 + F1 * F2 + 8 * 4 * F1) * (int)sizeof(float); // 114688
    if (!attr_done) {
        cudaFuncSetAttribute(k_fused, cudaFuncAttributeMaxDynamicSharedMemorySize, smem_bytes);
        attr_done = true;
    }

    k_zero_deg<<<(NN / 4 + 255) / 256, 256>>>();
    k_deg<<<(NE / 4 + 255) / 256, 256>>>((const int4*)src, (const int4*)dst);
    k_scan1<<<NB, 256>>>();
    k_scan2<<<1, 256>>>();
    k_scan3<<<NB, 256>>>();
    k_fill<<<(NE / 4 + 255) / 256, 256>>>((const int4*)src, (const int4*)dst);
    k_fused<<<(NN + RPB - 1) / RPB, 256, smem_bytes>>>(
        feat, (const float4*)W1, (const float4*)W2, b1);
    k_layer2<<<(NN / 2 * 32 + 255) / 256, 256>>>(out, b2);
}